// round 12
// baseline (speedup 1.0000x reference)
#include <cuda_runtime.h>

#define NS   128
#define NT   2048
#define NB   64
#define NTHR 512

// float-index offsets in dynamic smem
#define OFF_RING 0        // 32768: u64 ring[128 slots][128 j] = (v_ins, ref_ins)
#define OFF_PSH  32768    // 288:  [buf(2)][chunk(4) stride 36][32] exp(alpha - M)
#define OFF_PDUR 33056    // 1024: [buf][s][j] duration tail partials
#define OFF_FRR  34080    // 512:  u64 [buf][j] = (fac, ref)
#define OFF_W16  34592    // 32:   [buf][w] per-warp alpha maxes
#define OFF_MG   34624    // 4:    Mglob[t mod 4]
#define OFF_EFLG 34628    // 2 ints
#define OFF_FIN  34632    // 32
#define SMEM_FLOATS 34664  // ~135.4 KB

typedef unsigned long long u64;

__device__ __forceinline__ u64 pk2(float lo, float hi) {
    u64 r;
    asm("mov.b64 %0, {%1, %2};" : "=l"(r)
        : "r"(__float_as_uint(lo)), "r"(__float_as_uint(hi)));
    return r;
}
__device__ __forceinline__ void upk2(u64 v, float& lo, float& hi) {
    unsigned a, b;
    asm("mov.b64 {%0, %1}, %2;" : "=r"(a), "=r"(b) : "l"(v));
    lo = __uint_as_float(a); hi = __uint_as_float(b);
}
__device__ __forceinline__ u64 ffma2(u64 a, u64 b, u64 c) {
    u64 d;
    asm("fma.rn.f32x2 %0, %1, %2, %3;" : "=l"(d) : "l"(a), "l"(b), "l"(c));
    return d;
}
__device__ __forceinline__ unsigned f2key(float x) {
    int i = __float_as_int(x);
    return (unsigned)(i ^ ((i >> 31) | 0x80000000));
}
__device__ __forceinline__ float key2f(unsigned k) {
    int i = ((int)k < 0) ? (int)(k ^ 0x80000000u) : (int)(~k);
    return __int_as_float(i);
}
__device__ __forceinline__ float redux_max_f(float x) {
    unsigned r;
    asm volatile("redux.sync.max.u32 %0, %1, 0xffffffff;" : "=r"(r) : "r"(f2key(x)));
    return key2f(r);
}

__global__ __launch_bounds__(NTHR, 1)
void hsmm_fwd_kernel(const float* __restrict__ logB,
                     const float* __restrict__ pi,
                     const float* __restrict__ A,
                     const float* __restrict__ D,
                     float* __restrict__ out)
{
    extern __shared__ float smf[];
    u64*   ring64 = (u64*)(smf + OFF_RING);
    float* p_sh   = smf + OFF_PSH;
    float* pdur   = smf + OFF_PDUR;
    u64*   frref  = (u64*)(smf + OFF_FRR);
    float* w16    = smf + OFF_W16;
    float* Mglob  = smf + OFF_MG;
    int*   eflg   = (int*)(smf + OFF_EFLG);
    float* fin    = smf + OFF_FIN;

    const int tid  = threadIdx.x;
    const int b    = blockIdx.x;
    const int lane = tid & 31;
    const int w    = tid >> 5;
    const int jm   = tid >> 2;          // matvec/combine state
    const int sm2  = tid & 3;           // matvec slice (quad lane)
    const bool cse = (sm2 == 0);        // combine-active lane
    const int jd   = tid & 127;         // dur state
    const int sd   = tid >> 7;          // dur slice

    // ---------- register tables ----------
    u64   awt[16];      // packed exp(A) pairs: i = 32*sm2 + 2m, state jm
    float dwt[32];      // exp(D[jd][2+32sd+k])
    float q[32];        // circular window of slice-shifted v stream
    #pragma unroll
    for (int m = 0; m < 16; ++m) {
        int i0 = 32 * sm2 + 2 * m;
        awt[m] = pk2(__expf(A[i0 * NS + jm]), __expf(A[(i0 + 1) * NS + jm]));
    }
    #pragma unroll
    for (int k = 0; k < 32; ++k) {
        int c = 2 + 32 * sd + k;
        dwt[k] = (c < 128) ? __expf(D[jd * 128 + c]) : 0.0f;
        q[k] = 0.0f;
    }

    // ---------- init smem ----------
    for (int lin = tid; lin < 16384; lin += NTHR) ring64[lin] = 0ull;
    for (int lin = tid; lin < 1024;  lin += NTHR) pdur[lin] = 0.0f;
    if (tid < 288) p_sh[tid] = 0.0f;
    if (tid < 256) frref[tid] = pk2(1.0f, 0.0f);
    if (tid < 32)  w16[tid] = 0.0f;
    if (tid < 4)   Mglob[tid] = 0.0f;
    if (tid < 2)   eflg[tid] = -7;

    // combine scalars (live on cse lanes)
    float alpha = 0.f, cum = 0.f, ref = 0.f, v_prev = 0.f, fpend = 1.f;
    float lb_cur = 0.f, eD0 = 0.f, eD1 = 0.f;
    const float* lbp = logB + (size_t)b * NT * NS + jm;
    if (cse) {
        lb_cur = lbp[0];
        eD0 = __expf(D[jm * 128 + 0]);
        eD1 = __expf(D[jm * 128 + 1]);
    }
    __syncthreads();

    const u64 Z = 0ull;
    for (int tb = 0; tb < NT / 32; ++tb) {
        #pragma unroll
        for (int p = 0; p < 32; ++p) {
            const int t = (tb << 5) + p;

            // ---- matvec partial (quad layout) + intra-quad reduce ----
            float S = 0.0f;
            if (t > 0) {
                const float* psc = p_sh + (t & 1) * 144 + sm2 * 36;
                u64 a0 = Z, a1 = Z, a2 = Z, a3 = Z;
                #pragma unroll
                for (int k = 0; k < 8; ++k) {
                    ulonglong2 pv = *(const ulonglong2*)(psc + 4 * k);
                    if (k & 1) { a2 = ffma2(pv.x, awt[2 * k], a2); a3 = ffma2(pv.y, awt[2 * k + 1], a3); }
                    else       { a0 = ffma2(pv.x, awt[2 * k], a0); a1 = ffma2(pv.y, awt[2 * k + 1], a1); }
                }
                float x0, x1, y0, y1, z0, z1, u0, u1;
                upk2(a0, x0, x1); upk2(a1, y0, y1); upk2(a2, z0, z1); upk2(a3, u0, u1);
                float part = ((x0 + x1) + (y0 + y1)) + ((z0 + z1) + (u0 + u1));
                part += __shfl_xor_sync(0xffffffffu, part, 1);
                part += __shfl_xor_sync(0xffffffffu, part, 2);
                S = part;                     // valid on all quad lanes
            }

            // ---- combine (predicated: one lane per state, all warps) ----
            if (cse) {
                float tl0 = pdur[(t & 1) * 512 +   0 + jm];
                float tl1 = pdur[(t & 1) * 512 + 128 + jm];
                float tl2 = pdur[(t & 1) * 512 + 256 + jm];
                float tl3 = pdur[(t & 1) * 512 + 384 + jm];
                float v;
                if (t == 0) {
                    v = __expf(pi[jm]);
                } else {
                    float Mp = Mglob[(t - 1) & 3];        // scale used for p_sh at t-1
                    v = S * __expf(Mp - cum - ref);       // exp(entry_t - cum_t - ref)
                }
                float tail = (tl0 + tl1) + (tl2 + tl3);
                float dot = fmaf(fpend, tail, fmaf(eD1, v_prev, eD0 * v));

                cum += lb_cur;                            // cum[t+1]
                alpha = cum + ref + __logf(dot);
                lb_cur = (t + 1 < NT) ? lbp[(size_t)(t + 1) * NS] : 0.0f;

                bool sched = ((t & 15) == 15);
                bool emerg = (v > 1e13f);
                float ins, fac;
                if (emerg | (sched & (v > 1e-35f))) {
                    float lv = __logf(v);
                    ref += lv; ins = 1.0f; fac = __expf(-lv);
                    if (emerg & !sched) eflg[t & 1] = t;  // benign same-value race
                } else { ins = v; fac = 1.0f; }
                fpend = fac; v_prev = ins;
                frref[(t & 1) * 128 + jm] = pk2(fac, ref);
                ring64[(t & 127) * 128 + jm] = pk2(ins, ref);

                float Mn = Mglob[t & 3];                  // scale for p_sh at t
                p_sh[((t + 1) & 1) * 144 + (jm >> 5) * 36 + (jm & 31)] = __expf(alpha - Mn);
            }
            // per-warp alpha max (all lanes participate; idle lanes = -inf)
            {
                float av = cse ? alpha : -1e30f;
                float wm = redux_max_f(av);
                if (lane == 0) w16[((t + 1) & 1) * 16 + w] = wm;
            }
            // dedicated reducer warp: 16 warp-maxes (alpha_{t-1}) -> Mglob[(t+2)&3]
            if (w == 15) {
                float mv = (lane < 16) ? w16[(t & 1) * 16 + lane] : -1e30f;
                float gm = redux_max_f(mv);
                if (lane == 0) Mglob[(t + 2) & 3] = gm;
            }

            // ---- dur: 32-tap static circular window (all threads) ----
            {
                float fac, rn;
                upk2(frref[((t - 1) & 1) * 128 + jd], fac, rn);
                if (t > 0) {
                    bool rs = ((((t - 1) & 15) == 15) || (eflg[(t - 1) & 1] == t - 1));
                    if (rs) {
                        #pragma unroll
                        for (int k = 0; k < 32; ++k) q[k] *= fac;
                    }
                }
                const int bslot = (t - 1 - 32 * sd) & 127;   // v_{t-1-32sd}
                float bv, br;
                upk2(ring64[bslot * 128 + jd], bv, br);
                float nv = (br == rn) ? bv
                         : __expf(fminf(__logf(bv) + (br - rn), 85.0f));
                q[(p + 31) & 31] = nv;                       // q[(t-1) & 31]

                float c0 = 0.f, c1 = 0.f, c2 = 0.f, c3 = 0.f;
                #pragma unroll
                for (int k = 0; k < 32; k += 4) {
                    c0 = fmaf(q[(p + 31 - k) & 31], dwt[k + 0], c0);
                    c1 = fmaf(q[(p + 30 - k) & 31], dwt[k + 1], c1);
                    c2 = fmaf(q[(p + 29 - k) & 31], dwt[k + 2], c2);
                    c3 = fmaf(q[(p + 28 - k) & 31], dwt[k + 3], c3);
                }
                pdur[((t + 1) & 1) * 512 + sd * 128 + jd] = (c0 + c1) + (c2 + c3);
            }
            __syncthreads();                                 // single loop-carry barrier
        }
    }

    // ---------- loglik[b] = LSE_j alpha[T-1, j] ----------
    {
        float av = cse ? alpha : -1e30f;
        float wm = redux_max_f(av);
        if (lane == 0) fin[w] = wm;
    }
    __syncthreads();
    float m;
    {
        float4 f0 = *(const float4*)(fin + 0);
        float4 f1 = *(const float4*)(fin + 4);
        float4 f2 = *(const float4*)(fin + 8);
        float4 f3 = *(const float4*)(fin + 12);
        float m0 = fmaxf(fmaxf(f0.x, f0.y), fmaxf(f0.z, f0.w));
        float m1 = fmaxf(fmaxf(f1.x, f1.y), fmaxf(f1.z, f1.w));
        float m2 = fmaxf(fmaxf(f2.x, f2.y), fmaxf(f2.z, f2.w));
        float m3 = fmaxf(fmaxf(f3.x, f3.y), fmaxf(f3.z, f3.w));
        m = fmaxf(fmaxf(m0, m1), fmaxf(m2, m3));
    }
    {
        float e = cse ? __expf(alpha - m) : 0.0f;
        #pragma unroll
        for (int o = 16; o > 0; o >>= 1)
            e += __shfl_xor_sync(0xffffffffu, e, o);
        if (lane == 0) fin[16 + w] = e;
    }
    __syncthreads();
    if (tid == 0) {
        float ssum = 0.0f;
        #pragma unroll
        for (int k = 0; k < 16; ++k) ssum += fin[16 + k];
        out[b] = m + __logf(ssum);
    }
}

extern "C" void kernel_launch(void* const* d_in, const int* in_sizes, int n_in,
                              void* d_out, int out_size)
{
    const float* logB = (const float*)d_in[0];
    const float* pi   = (const float*)d_in[1];
    const float* A    = (const float*)d_in[2];
    const float* D    = (const float*)d_in[3];
    float* out = (float*)d_out;

    const size_t smem_bytes = (size_t)SMEM_FLOATS * sizeof(float);  // ~135.4 KB
    cudaFuncSetAttribute(hsmm_fwd_kernel,
                         cudaFuncAttributeMaxDynamicSharedMemorySize,
                         (int)smem_bytes);
    hsmm_fwd_kernel<<<NB, NTHR, smem_bytes>>>(logB, pi, A, D, out);
}

// round 13
// speedup vs baseline: 1.4971x; 1.4971x over previous
#include <cuda_runtime.h>

#define NS   128
#define NT   2048
#define NB   64
#define NTHR 512   // 4 slices (s=tid>>7) x 128 states; tid<128 also combine

// float-index offsets in dynamic smem (R10 layout, minus eD01)
#define OFF_RING 0       // 32768: u64 ring[128 slots][128 j] = (v_ins, ref_ins)
#define OFF_PSH  32768   // 256:  [buf][j] exp(alpha - M)
#define OFF_PMAT 33024   // 512:  [s][j] matvec partials
#define OFF_PDUR 33536   // 1024: [buf][s][j] duration tail partials
#define OFF_FLAG 34560   // 256:  [buf][j] rescale factor
#define OFF_REFS 34816   // 256:  [buf][j] ref after that step
#define OFF_WRED 35072   // 8:    [buf][w] per-warp alpha maxes
#define OFF_EFLG 35080   // 2 ints: emergency-rescale generation, by parity
#define OFF_FIN  35084   // 16
#define SMEM_FLOATS 35104  // ~137.1 KB

typedef unsigned long long u64;

__device__ __forceinline__ u64 pk2(float lo, float hi) {
    u64 r;
    asm("mov.b64 %0, {%1, %2};" : "=l"(r)
        : "r"(__float_as_uint(lo)), "r"(__float_as_uint(hi)));
    return r;
}
__device__ __forceinline__ void upk2(u64 v, float& lo, float& hi) {
    unsigned a, b;
    asm("mov.b64 {%0, %1}, %2;" : "=r"(a), "=r"(b) : "l"(v));
    lo = __uint_as_float(a); hi = __uint_as_float(b);
}
__device__ __forceinline__ u64 ffma2(u64 a, u64 b, u64 c) {
    u64 d;
    asm("fma.rn.f32x2 %0, %1, %2, %3;" : "=l"(d) : "l"(a), "l"(b), "l"(c));
    return d;
}
__device__ __forceinline__ unsigned f2key(float x) {
    int i = __float_as_int(x);
    return (unsigned)(i ^ ((i >> 31) | 0x80000000));
}
__device__ __forceinline__ float key2f(unsigned k) {
    int i = ((int)k < 0) ? (int)(k ^ 0x80000000u) : (int)(~k);
    return __int_as_float(i);
}

__global__ __launch_bounds__(NTHR, 1)
void hsmm_fwd_kernel(const float* __restrict__ logB,
                     const float* __restrict__ pi,
                     const float* __restrict__ A,
                     const float* __restrict__ D,
                     float* __restrict__ out)
{
    extern __shared__ float sm[];
    u64*   ring64 = (u64*)(sm + OFF_RING);
    float* p_sh   = sm + OFF_PSH;
    float* pmat   = sm + OFF_PMAT;
    float* pdur   = sm + OFF_PDUR;
    float* flagS  = sm + OFF_FLAG;
    float* refsS  = sm + OFF_REFS;
    float* wred   = sm + OFF_WRED;
    int*   eflg   = (int*)(sm + OFF_EFLG);
    float* fin    = sm + OFF_FIN;

    const int tid  = threadIdx.x;
    const int b    = blockIdx.x;
    const int lane = tid & 31;
    const int w    = tid >> 5;
    const int j    = tid & 127;
    const int s    = tid >> 7;          // slice 0..3

    // ---------- register tables ----------
    u64   awt[16];      // packed exp(A) pairs for matvec slice s
    float dwt[32];      // exp(D) taps, d-1 = 2+32s+k
    float q[32];        // circular window: q[tau & 31] = v_tau
    #pragma unroll
    for (int m = 0; m < 16; ++m) {
        int i0 = 32 * s + 2 * m;
        awt[m] = pk2(__expf(A[i0 * NS + j]), __expf(A[(i0 + 1) * NS + j]));
    }
    #pragma unroll
    for (int k = 0; k < 32; ++k) {
        int c = 2 + 32 * s + k;
        dwt[k] = (c < 128) ? __expf(D[j * 128 + c]) : 0.0f;
        q[k] = 0.0f;
    }

    // ---------- init smem ----------
    for (int lin = tid; lin < 16384; lin += NTHR) ring64[lin] = 0ull;
    for (int lin = tid; lin < 1024;  lin += NTHR) pdur[lin] = 0.0f;
    if (tid < 128) {
        p_sh[tid] = 0.0f;  p_sh[128 + tid] = 0.0f;
        flagS[tid] = 1.0f; flagS[128 + tid] = 1.0f;
        refsS[tid] = 0.0f; refsS[128 + tid] = 0.0f;
    }
    if (tid < 8) wred[tid] = 0.0f;
    if (tid < 2) eflg[tid] = -7;

    // combine-role scalars (tid<128)
    float alpha = 0.f, cum = 0.f, ref = 0.f, v_prev = 0.f, fpend = 1.f, Mprev = 0.f;
    float lb_cur = 0.f, eD0 = 0.f, eD1 = 0.f;
    const float* lbp = logB + (size_t)b * NT * NS + j;
    if (tid < 128) {
        lb_cur = lbp[0];
        eD0 = __expf(D[j * 128 + 0]);
        eD1 = __expf(D[j * 128 + 1]);
    }
    __syncthreads();

    const u64 Z = 0ull;
    for (int tb = 0; tb < NT / 32; ++tb) {
        #pragma unroll
        for (int p = 0; p < 32; ++p) {
            const int t = (tb << 5) + p;

            // ================= Phase A =================
            // hoisted combine prologue (reads only step t-1 buffers + registers)
            float tail = 0.f, Mnow = 0.f, K = 0.f, base = 0.f;
            if (tid < 128) {
                float tl0 = pdur[(t & 1) * 512 +   0 + j];
                float tl1 = pdur[(t & 1) * 512 + 128 + j];
                float tl2 = pdur[(t & 1) * 512 + 256 + j];
                float tl3 = pdur[(t & 1) * 512 + 384 + j];
                tail = (tl0 + tl1) + (tl2 + tl3);
                float4 wr4 = *(const float4*)(wred + (t & 1) * 4);
                Mnow = fmaxf(fmaxf(wr4.x, wr4.y), fmaxf(wr4.z, wr4.w));
                K = __expf(Mprev - cum - ref);          // scale for v (uses cum_old)
                cum += lb_cur;                          // cum[t+1]
                base = cum + ref;
                lb_cur = lbp[(size_t)((t + 1 < NT) ? t + 1 : t) * NS];  // early issue
            }
            // trans matvec partial (all threads)
            if (t > 0) {
                const float* psc = p_sh + (t & 1) * 128 + 32 * s;
                u64 a0 = Z, a1 = Z, a2 = Z, a3 = Z;
                #pragma unroll
                for (int k = 0; k < 8; ++k) {
                    ulonglong2 pv = *(const ulonglong2*)(psc + 4 * k);   // broadcast
                    if (k & 1) { a2 = ffma2(pv.x, awt[2 * k], a2); a3 = ffma2(pv.y, awt[2 * k + 1], a3); }
                    else       { a0 = ffma2(pv.x, awt[2 * k], a0); a1 = ffma2(pv.y, awt[2 * k + 1], a1); }
                }
                float x0, x1, y0, y1, z0, z1, u0, u1;
                upk2(a0, x0, x1); upk2(a1, y0, y1); upk2(a2, z0, z1); upk2(a3, u0, u1);
                pmat[s * 128 + j] = ((x0 + x1) + (y0 + y1)) + ((z0 + z1) + (u0 + u1));
            }
            __syncthreads();                                   // sync1: pmat ready

            // ================= Phase B ==================================================
            if (tid < 128) {
                // ---- combine: short post-barrier chain ----
                float v;
                if (t == 0) {
                    v = __expf(pi[j]);
                } else {
                    float S = (pmat[j] + pmat[128 + j]) + (pmat[256 + j] + pmat[384 + j]);
                    v = S * K;                            // exp(entry_t - cum_t - ref)
                }
                float dot = fmaf(fpend, tail, fmaf(eD1, v_prev, eD0 * v));
                alpha = base + __logf(dot);

                bool sched = ((t & 15) == 15);
                bool emerg = (v > 1e13f);
                float ins, fac;
                if (emerg | (sched & (v > 1e-35f))) {
                    float lv = __logf(v);
                    ref += lv; ins = 1.0f; fac = __expf(-lv);
                    if (emerg & !sched) eflg[t & 1] = t;  // benign same-value race
                } else { ins = v; fac = 1.0f; }
                fpend = fac; v_prev = ins;
                flagS[(t & 1) * 128 + j] = fac;
                refsS[(t & 1) * 128 + j] = ref;
                ring64[(t & 127) * 128 + j] = pk2(ins, ref);

                p_sh[((t + 1) & 1) * 128 + j] = __expf(alpha - Mnow);
                Mprev = Mnow;

                unsigned ku = f2key(alpha), r;
                asm volatile("redux.sync.max.u32 %0, %1, 0xffffffff;" : "=r"(r) : "r"(ku));
                if (lane == 0) wred[((t + 1) & 1) * 4 + w] = key2f(r);
            }

            // ---- dur: 32-tap static circular window in registers (all threads) ----
            {
                if (t > 0) {
                    bool rs = ((((t - 1) & 15) == 15) || (eflg[(t - 1) & 1] == t - 1));
                    if (rs) {
                        float fac = flagS[((t - 1) & 1) * 128 + j];
                        #pragma unroll
                        for (int k = 0; k < 32; ++k) q[k] *= fac;
                    }
                }
                const int bslot = (t - 1 - 32 * s) & 127;     // v_{t-1-32s}
                float bv, br;
                upk2(ring64[bslot * 128 + j], bv, br);
                float rn = refsS[((t - 1) & 1) * 128 + j];
                float nv = (br == rn) ? bv
                         : __expf(fminf(__logf(bv) + (br - rn), 85.0f));
                q[(p + 31) & 31] = nv;                        // q[(t-1) & 31], static index

                float c0 = 0.f, c1 = 0.f, c2 = 0.f, c3 = 0.f;
                #pragma unroll
                for (int k = 0; k < 32; k += 4) {
                    c0 = fmaf(q[(p + 31 - k) & 31], dwt[k + 0], c0);
                    c1 = fmaf(q[(p + 30 - k) & 31], dwt[k + 1], c1);
                    c2 = fmaf(q[(p + 29 - k) & 31], dwt[k + 2], c2);
                    c3 = fmaf(q[(p + 28 - k) & 31], dwt[k + 3], c3);
                }
                pdur[((t + 1) & 1) * 512 + s * 128 + j] = (c0 + c1) + (c2 + c3);
            }
            __syncthreads();                                   // sync2: loop carry
        }
    }

    // ---------- loglik[b] = LSE_j alpha[T-1, j] ----------
    if (tid < 128) {
        float mv = alpha;
        #pragma unroll
        for (int o = 16; o > 0; o >>= 1)
            mv = fmaxf(mv, __shfl_xor_sync(0xffffffffu, mv, o));
        if (lane == 0) fin[w] = mv;
    }
    __syncthreads();
    float m = fmaxf(fmaxf(fin[0], fin[1]), fmaxf(fin[2], fin[3]));
    if (tid < 128) {
        float e = __expf(alpha - m);
        #pragma unroll
        for (int o = 16; o > 0; o >>= 1)
            e += __shfl_xor_sync(0xffffffffu, e, o);
        if (lane == 0) fin[8 + w] = e;
    }
    __syncthreads();
    if (tid == 0) {
        float ssum = (fin[8] + fin[9]) + (fin[10] + fin[11]);
        out[b] = m + __logf(ssum);
    }
}

extern "C" void kernel_launch(void* const* d_in, const int* in_sizes, int n_in,
                              void* d_out, int out_size)
{
    const float* logB = (const float*)d_in[0];
    const float* pi   = (const float*)d_in[1];
    const float* A    = (const float*)d_in[2];
    const float* D    = (const float*)d_in[3];
    float* out = (float*)d_out;

    const size_t smem_bytes = (size_t)SMEM_FLOATS * sizeof(float);  // ~137.1 KB
    cudaFuncSetAttribute(hsmm_fwd_kernel,
                         cudaFuncAttributeMaxDynamicSharedMemorySize,
                         (int)smem_bytes);
    hsmm_fwd_kernel<<<NB, NTHR, smem_bytes>>>(logB, pi, A, D, out);
}